// round 3
// baseline (speedup 1.0000x reference)
#include <cuda_runtime.h>

#define Bb 32
#define Cc 3
#define Hh 512
#define Ww 512
#define NPIX (Hh*Ww)
#define CUTSZ 128
#define PARTS 16

#define TW 64
#define TH 32
#define SSTR 72               // max src bbox width  (<= 71)
#define SROWS 45              // max src bbox height (<= 45)
#define SPLANE (SSTR*SROWS)   // 3240 floats per channel plane
#define AUG_SMEM (3*SPLANE*4) // 38880 bytes

// Scratch (no allocations allowed)
__device__ float g_part[Bb*Cc*PARTS];

// ---------------------------------------------------------------------------
// Kernel 1: per-(b,c) partial sums of clip(img + bf, -1, 1)
// 1536 blocks x 256 threads; each block sums 16384 contiguous floats.
// ---------------------------------------------------------------------------
__global__ void __launch_bounds__(256) mean_partial(const float* __restrict__ img,
                                                    const float* __restrict__ u_bright)
{
    int bc   = blockIdx.x / PARTS;
    int part = blockIdx.x % PARTS;
    int b    = bc / Cc;
    float bf = (u_bright[b] * 2.0f - 1.0f) * 0.2f;

    const float4* p = (const float4*)(img + (size_t)bc * NPIX + (size_t)part * (NPIX / PARTS));
    int t = threadIdx.x;
    float s0 = 0.0f, s1 = 0.0f, s2 = 0.0f, s3 = 0.0f;
#pragma unroll
    for (int i = 0; i < 16; i += 4) {
        float4 v0 = p[t + (i + 0) * 256];
        float4 v1 = p[t + (i + 1) * 256];
        float4 v2 = p[t + (i + 2) * 256];
        float4 v3 = p[t + (i + 3) * 256];
        s0 += fminf(fmaxf(v0.x + bf, -1.0f), 1.0f) + fminf(fmaxf(v0.y + bf, -1.0f), 1.0f)
            + fminf(fmaxf(v0.z + bf, -1.0f), 1.0f) + fminf(fmaxf(v0.w + bf, -1.0f), 1.0f);
        s1 += fminf(fmaxf(v1.x + bf, -1.0f), 1.0f) + fminf(fmaxf(v1.y + bf, -1.0f), 1.0f)
            + fminf(fmaxf(v1.z + bf, -1.0f), 1.0f) + fminf(fmaxf(v1.w + bf, -1.0f), 1.0f);
        s2 += fminf(fmaxf(v2.x + bf, -1.0f), 1.0f) + fminf(fmaxf(v2.y + bf, -1.0f), 1.0f)
            + fminf(fmaxf(v2.z + bf, -1.0f), 1.0f) + fminf(fmaxf(v2.w + bf, -1.0f), 1.0f);
        s3 += fminf(fmaxf(v3.x + bf, -1.0f), 1.0f) + fminf(fmaxf(v3.y + bf, -1.0f), 1.0f)
            + fminf(fmaxf(v3.z + bf, -1.0f), 1.0f) + fminf(fmaxf(v3.w + bf, -1.0f), 1.0f);
    }
    float s = (s0 + s1) + (s2 + s3);
#pragma unroll
    for (int o = 16; o > 0; o >>= 1) s += __shfl_xor_sync(0xffffffffu, s, o);
    __shared__ float sh[8];
    if ((t & 31) == 0) sh[t >> 5] = s;
    __syncthreads();
    if (t == 0) {
        float tot = sh[0] + sh[1] + sh[2] + sh[3] + sh[4] + sh[5] + sh[6] + sh[7];
        g_part[blockIdx.x] = tot;
    }
}

// ---------------------------------------------------------------------------
// Per-pixel color transform: brightness -> contrast -> HSV adjust -> RGB
// ---------------------------------------------------------------------------
__device__ __forceinline__ float3 color_xform(float cr, float cg, float cb,
                                              float bf, float cf,
                                              float mr, float mg, float mb2,
                                              float dh, float sf)
{
    cr = fminf(fmaxf(cr + bf, -1.0f), 1.0f);
    cg = fminf(fmaxf(cg + bf, -1.0f), 1.0f);
    cb = fminf(fmaxf(cb + bf, -1.0f), 1.0f);
    cr = fminf(fmaxf((cr - mr)  * cf + mr,  -1.0f), 1.0f);
    cg = fminf(fmaxf((cg - mg)  * cf + mg,  -1.0f), 1.0f);
    cb = fminf(fmaxf((cb - mb2) * cf + mb2, -1.0f), 1.0f);

    float mx = fmaxf(cr, fmaxf(cg, cb));
    float mn = fminf(cr, fminf(cg, cb));
    float d  = mx - mn;
    float invd = (d == 0.0f) ? 1.0f : __fdividef(1.0f, d);

    float tr = (cg - cb) * invd;
    float hr = tr * (1.0f / 6.0f);
    hr = (tr < 0.0f) ? hr + 1.0f : hr;
    float hg = fmaf((cb - cr) * invd, 1.0f / 6.0f, 2.0f / 6.0f);
    float hb = fmaf((cr - cg) * invd, 1.0f / 6.0f, 4.0f / 6.0f);
    float hch = (mx == cb) ? hb : ((mx == cg) ? hg : ((mx == cr) ? hr : 0.0f));

    float c = (mx > 0.0f) ? fminf(d * sf, mx) : 0.0f;
    float hp = fminf(fmaxf(hch + dh, 0.0f), 1.0f);

    float t6 = hp * 6.0f;
    float m2 = t6 - 2.0f * floorf(t6 * 0.5f);
    float xv = c * (1.0f - fabsf(m2 - 1.0f));
    float m  = mx - c;
    int seg  = (int)t6;
    float rr = (seg == 0 || seg == 5) ? c : ((seg == 1 || seg == 4) ? xv : 0.0f);
    float gg = (seg == 1 || seg == 2) ? c : ((seg == 0 || seg == 3) ? xv : 0.0f);
    float bb = (seg == 3 || seg == 4) ? c : ((seg == 2 || seg == 5) ? xv : 0.0f);
    return make_float3(rr + m, gg + m, bb + m);
}

// ---------------------------------------------------------------------------
// Kernel 2: smem-tiled — transform each source pixel ONCE (zero-fill OOB),
// then branch-free bilinear sampling. 64x32 output tile, 512 threads.
// ---------------------------------------------------------------------------
__global__ void __launch_bounds__(512, 3) aug_kernel(
    const float* __restrict__ img,
    const float* __restrict__ u_bright,
    const float* __restrict__ u_contrast,
    const float* __restrict__ u_hue,
    const float* __restrict__ u_sat,
    const float* __restrict__ u_angle,
    const float* __restrict__ noise,
    const int*   __restrict__ cutout_xy,
    const int*   __restrict__ cutout_apply,
    float*       __restrict__ out)
{
    extern __shared__ float sm[];   // [3][SPLANE]
    int b  = blockIdx.z;
    int w0 = blockIdx.x * TW;
    int h0 = blockIdx.y * TH;
    int t  = threadIdx.x;

    // Per-batch params
    float bf  = (u_bright[b]   * 2.0f - 1.0f) * 0.2f;
    float cf  = 1.0f + (u_contrast[b] * 2.0f - 1.0f) * 0.2f;
    float dh  = (u_hue[b]      * 2.0f - 1.0f) * 0.1f;
    float sf  = 1.0f + (u_sat[b]      * 2.0f - 1.0f) * 0.2f;
    float ang = (u_angle[b]    * 2.0f - 1.0f) * 0.17453292519943295f;
    float sa, ca;
    sincosf(ang, &sa, &ca);

    // Inline mean finalize (uniform across block; cheap, saves a launch)
    const float inv = 1.0f / (float)NPIX;
    float mr = 0.0f, mg = 0.0f, mb2 = 0.0f;
#pragma unroll
    for (int k = 0; k < PARTS; k++) {
        mr  += g_part[(b * 3 + 0) * PARTS + k];
        mg  += g_part[(b * 3 + 1) * PARTS + k];
        mb2 += g_part[(b * 3 + 2) * PARTS + k];
    }
    mr *= inv; mg *= inv; mb2 *= inv;

    const float s2 = 2.0f / 511.0f;
    // Source bbox of this output tile (rotation linear -> extremes at corners)
    float xxl = fmaf((float)w0,            s2, -1.0f);
    float xxh = fmaf((float)(w0 + TW - 1), s2, -1.0f);
    float yyl = fmaf((float)h0,            s2, -1.0f);
    float yyh = fmaf((float)(h0 + TH - 1), s2, -1.0f);

    float gx00 = ca * xxl - sa * yyl, gx01 = ca * xxh - sa * yyl;
    float gx10 = ca * xxl - sa * yyh, gx11 = ca * xxh - sa * yyh;
    float gy00 = sa * xxl + ca * yyl, gy01 = sa * xxh + ca * yyl;
    float gy10 = sa * xxl + ca * yyh, gy11 = sa * xxh + ca * yyh;

    float pxmin = fminf(fminf(gx00, gx01), fminf(gx10, gx11));
    float pxmax = fmaxf(fmaxf(gx00, gx01), fmaxf(gx10, gx11));
    float pymin = fminf(fminf(gy00, gy01), fminf(gy10, gy11));
    float pymax = fmaxf(fmaxf(gy00, gy01), fmaxf(gy10, gy11));

    int xs = (int)floorf((pxmin + 1.0f) * 256.0f - 0.5f);
    int xe = (int)floorf((pxmax + 1.0f) * 256.0f - 0.5f) + 1;
    int ys = (int)floorf((pymin + 1.0f) * 256.0f - 0.5f);
    int ye = (int)floorf((pymax + 1.0f) * 256.0f - 0.5f) + 1;
    int sw = xe - xs + 1; if (sw > SSTR)  sw = SSTR;
    int sh = ye - ys + 1; if (sh > SROWS) sh = SROWS;

    // Load + transform source region into smem (ONCE per src pixel).
    // Out-of-image pixels get exact 0 (matches reference's gather()*valid).
    const float* base = img + (size_t)b * Cc * NPIX;
    int total = sw * sh;
    for (int i = t; i < total; i += 512) {
        int ly = i / sw;
        int lx = i - ly * sw;
        int xi = xs + lx;
        int yi = ys + ly;
        float3 c = make_float3(0.0f, 0.0f, 0.0f);
        if (xi >= 0 && xi < Ww && yi >= 0 && yi < Hh) {
            int off = (Hh - 1 - yi) * Ww + xi;   // vertical flip
            float r  = __ldg(base + off);
            float g  = __ldg(base + NPIX + off);
            float bl = __ldg(base + 2 * NPIX + off);
            c = color_xform(r, g, bl, bf, cf, mr, mg, mb2, dh, sf);
        }
        int si = ly * SSTR + lx;
        sm[si]              = c.x;
        sm[si + SPLANE]     = c.y;
        sm[si + 2 * SPLANE] = c.z;
    }
    __syncthreads();

    // Sampling phase: 512 threads cover 64x32 outputs (4 px/thread), branch-free
    int tx = t & 31;        // 0..31
    int ty = t >> 5;        // 0..15

    int cx = cutout_xy[b * 2 + 0];
    int cy = cutout_xy[b * 2 + 1];
    bool apply = (cutout_apply[b] != 0);

#pragma unroll
    for (int dy = 0; dy < 2; dy++) {
#pragma unroll
        for (int dx = 0; dx < 2; dx++) {
            int w = w0 + tx + dx * 32;
            int h = h0 + ty + dy * 16;

            float xx = fmaf((float)w, s2, -1.0f);
            float yy = fmaf((float)h, s2, -1.0f);
            float gxp = (ca * xx - sa * yy + 1.0f) * 256.0f - 0.5f;
            float gyp = (sa * xx + ca * yy + 1.0f) * 256.0f - 0.5f;
            float x0f = floorf(gxp), y0f = floorf(gyp);
            float wx = gxp - x0f, wy = gyp - y0f;
            int x0 = (int)x0f, y0 = (int)y0f;

            float w11 = wy * wx;
            float w10 = wy - w11;
            float w01 = wx - w11;
            float w00 = 1.0f - wy - wx + w11;

            int si = (y0 - ys) * SSTR + (x0 - xs);

            float accr = sm[si] * w00
                       + sm[si + 1] * w01
                       + sm[si + SSTR] * w10
                       + sm[si + SSTR + 1] * w11;
            float accg = sm[si + SPLANE] * w00
                       + sm[si + SPLANE + 1] * w01
                       + sm[si + SPLANE + SSTR] * w10
                       + sm[si + SPLANE + SSTR + 1] * w11;
            float accb = sm[si + 2 * SPLANE] * w00
                       + sm[si + 2 * SPLANE + 1] * w01
                       + sm[si + 2 * SPLANE + SSTR] * w10
                       + sm[si + 2 * SPLANE + SSTR + 1] * w11;

            size_t o = (size_t)b * Cc * NPIX + (size_t)h * Ww + w;
            float nr = __ldcs(noise + o);
            float ng = __ldcs(noise + o + NPIX);
            float nb = __ldcs(noise + o + 2 * NPIX);
            accr = fminf(fmaxf(fmaf(nr, 0.05f, accr), -1.0f), 1.0f);
            accg = fminf(fmaxf(fmaf(ng, 0.05f, accg), -1.0f), 1.0f);
            accb = fminf(fmaxf(fmaf(nb, 0.05f, accb), -1.0f), 1.0f);

            bool cut = apply && (h >= cy) && (h < cy + CUTSZ) &&
                               (w >= cx) && (w < cx + CUTSZ);
            if (cut) { accr = 0.0f; accg = 0.0f; accb = 0.0f; }

            __stcs(out + o,            accr);
            __stcs(out + o + NPIX,     accg);
            __stcs(out + o + 2 * NPIX, accb);
        }
    }
}

// ---------------------------------------------------------------------------
extern "C" void kernel_launch(void* const* d_in, const int* in_sizes, int n_in,
                              void* d_out, int out_size)
{
    const float* img        = (const float*)d_in[0];
    const float* u_bright   = (const float*)d_in[1];
    const float* u_contrast = (const float*)d_in[2];
    const float* u_hue      = (const float*)d_in[3];
    const float* u_sat      = (const float*)d_in[4];
    const float* u_angle    = (const float*)d_in[5];
    const float* noise      = (const float*)d_in[6];
    const int*   cutout_xy  = (const int*)d_in[7];
    const int*   cutout_ap  = (const int*)d_in[8];
    float* out = (float*)d_out;

    cudaFuncSetAttribute(aug_kernel, cudaFuncAttributeMaxDynamicSharedMemorySize, AUG_SMEM);

    mean_partial<<<Bb * Cc * PARTS, 256>>>(img, u_bright);

    dim3 grd(Ww / TW, Hh / TH, Bb);
    aug_kernel<<<grd, 512, AUG_SMEM>>>(img, u_bright, u_contrast, u_hue, u_sat,
                                       u_angle, noise, cutout_xy, cutout_ap, out);
}